// round 2
// baseline (speedup 1.0000x reference)
#include <cuda_runtime.h>
#include <cuda_bf16.h>
#include <cstdint>

#define DIM   768
#define INNER 96
#define NTOK  8
#define HW    1024
#define NB    64
#define EPS_LN 1e-5f

typedef unsigned long long ull;

// ---------------- scratch (device globals; no allocation allowed) ------------
__device__ __nv_bfloat16 g_Wt[INNER * DIM];        // W1*gamma, bf16, [i][c] (transposed)
__device__ float g_colsum[INNER];                  // sum_c gamma[c]*w1[c,i]
__device__ float g_bw1[INNER];                     // b1[i] + sum_c beta[c]*w1[c,i]
__device__ float g_r[NB * HW];                     // rsqrt(var+eps) per token
__device__ float g_mu[NB * HW];                    // mean per token
__device__ float g_logitsT[NB * NTOK * HW];        // logits, [b][n][p]
__device__ float g_attnwT[NB * NTOK * HW];         // r_p * attn[p,n], [b][n][p]
__device__ float g_S[NB * NTOK];                   // sum_p mu_p r_p attn[p,n]

// ---------------- helpers ----------------------------------------------------
__device__ __forceinline__ uint32_t lds_b32(const __nv_bfloat16* p) {
    return *reinterpret_cast<const uint32_t*>(p);
}

__device__ __forceinline__ void mma_bf16(float* d,
    uint32_t a0, uint32_t a1, uint32_t a2, uint32_t a3,
    uint32_t b0, uint32_t b1)
{
    asm volatile(
        "mma.sync.aligned.m16n8k16.row.col.f32.bf16.bf16.f32 "
        "{%0,%1,%2,%3}, {%4,%5,%6,%7}, {%8,%9}, {%0,%1,%2,%3};"
        : "+f"(d[0]), "+f"(d[1]), "+f"(d[2]), "+f"(d[3])
        : "r"(a0), "r"(a1), "r"(a2), "r"(a3), "r"(b0), "r"(b1));
}

__device__ __forceinline__ void fma2(ull& d, ull a, ull b) {
    asm volatile("fma.rn.f32x2 %0, %1, %2, %0;" : "+l"(d) : "l"(a), "l"(b));
}

// ---------------- setup: fold gamma into W1, precompute column sums ----------
__global__ void setup_kernel(const float* __restrict__ w1,
                             const float* __restrict__ gamma,
                             const float* __restrict__ beta,
                             const float* __restrict__ b1)
{
    int i = blockIdx.x;          // 0..95
    int t = threadIdx.x;         // 256
    float a = 0.f, bs = 0.f;
    for (int c = t; c < DIM; c += 256) {
        float w  = w1[c * INNER + i];
        float gw = gamma[c] * w;
        g_Wt[i * DIM + c] = __float2bfloat16(gw);
        a  += gw;
        bs += beta[c] * w;
    }
    __shared__ float ra[256], rb[256];
    ra[t] = a; rb[t] = bs;
    __syncthreads();
    for (int s = 128; s > 0; s >>= 1) {
        if (t < s) { ra[t] += ra[t + s]; rb[t] += rb[t + s]; }
        __syncthreads();
    }
    if (t == 0) {
        g_colsum[i] = ra[0];
        g_bw1[i]    = rb[0] + b1[i];
    }
}

// ---------------- pass A: LN stats + MLP logits via bf16 mma ------------------
// Block: 128 tokens (one q-tile) of one batch. GEMM: [128 q] x [768 c] x [96 i].
constexpr int XP = 34;   // Xs pitch in bf16 (32 + 2 pad)
constexpr int WP = 40;   // Ws pitch in bf16 (32 + 8 pad) -> conflict-free B reads

__global__ __launch_bounds__(256, 2) void passA_kernel(
    const float* __restrict__ x, const float* __restrict__ w2)
{
    __shared__ __nv_bfloat16 Xs[128 * XP];
    __shared__ __nv_bfloat16 Ws[INNER * WP];
    __shared__ float logitsS[128 * NTOK];
    __shared__ float sumS[128], sqS[128], muS[128], rS[128];
    __shared__ float w2S[INNER * NTOK];
    __shared__ float colsumS[INNER], bw1S[INNER];

    int t   = threadIdx.x;
    int blk = blockIdx.x;
    int b   = blk >> 3;
    int q0  = (blk & 7) << 7;

    for (int i = t; i < 128 * NTOK; i += 256) logitsS[i] = 0.f;
    if (t < 128) { sumS[t] = 0.f; sqS[t] = 0.f; }
    for (int i = t; i < INNER * NTOK; i += 256) w2S[i] = w2[i];
    if (t < INNER) { colsumS[t] = g_colsum[t]; bw1S[t] = g_bw1[t]; }

    int qi = t & 63;        // token pair index: handles q = 2*qi, 2*qi+1
    int ci = t >> 6;        // channel slice 0..3
    const float* xb = x + ((size_t)b * DIM) * HW + q0 + qi * 2;

    float s1a = 0.f, s1b = 0.f, s2a = 0.f, s2b = 0.f;
    float acc[2][6][4];
#pragma unroll
    for (int mt = 0; mt < 2; mt++)
#pragma unroll
        for (int nt = 0; nt < 6; nt++)
#pragma unroll
            for (int r = 0; r < 4; r++) acc[mt][nt][r] = 0.f;

    int w    = t >> 5, lane = t & 31;
    int wm   = w & 3,  wn   = w >> 2;      // warp tile: 32 q x 48 i
    int gid  = lane >> 2, tid = lane & 3;
    int wi   = t >> 1, whf = t & 1;        // W-tile loader mapping (t<192)

    for (int kc = 0; kc < 24; kc++) {
        int c0 = kc * 32;
        float2 xv[8];
#pragma unroll
        for (int j = 0; j < 8; j++)
            xv[j] = *(const float2*)(xb + (size_t)(c0 + ci * 8 + j) * HW);
        uint4 wv0, wv1;
        if (t < 192) {
            const uint4* src = (const uint4*)(g_Wt + wi * DIM + c0 + whf * 16);
            wv0 = src[0]; wv1 = src[1];
        }
        __syncthreads();
#pragma unroll
        for (int j = 0; j < 8; j++) {
            float a0 = xv[j].x, a1 = xv[j].y;
            s1a += a0; s2a += a0 * a0;
            s1b += a1; s2b += a1 * a1;
            int c = ci * 8 + j;
            Xs[(qi * 2)     * XP + c] = __float2bfloat16(a0);
            Xs[(qi * 2 + 1) * XP + c] = __float2bfloat16(a1);
        }
        if (t < 192) {
            uint4* dst = (uint4*)(Ws + wi * WP + whf * 16);
            dst[0] = wv0; dst[1] = wv1;
        }
        __syncthreads();
#pragma unroll
        for (int ks = 0; ks < 2; ks++) {
            uint32_t af[2][4];
#pragma unroll
            for (int mt = 0; mt < 2; mt++) {
                int qr = wm * 32 + mt * 16 + gid;
                int cb = ks * 16 + tid * 2;
                af[mt][0] = lds_b32(&Xs[qr * XP + cb]);
                af[mt][1] = lds_b32(&Xs[(qr + 8) * XP + cb]);
                af[mt][2] = lds_b32(&Xs[qr * XP + cb + 8]);
                af[mt][3] = lds_b32(&Xs[(qr + 8) * XP + cb + 8]);
            }
#pragma unroll
            for (int nt = 0; nt < 6; nt++) {
                int ib = wn * 48 + nt * 8 + gid;
                uint32_t b0 = lds_b32(&Ws[ib * WP + ks * 16 + tid * 2]);
                uint32_t b1 = lds_b32(&Ws[ib * WP + ks * 16 + 8 + tid * 2]);
                mma_bf16(acc[0][nt], af[0][0], af[0][1], af[0][2], af[0][3], b0, b1);
                mma_bf16(acc[1][nt], af[1][0], af[1][1], af[1][2], af[1][3], b0, b1);
            }
        }
    }

    // token stats
    atomicAdd(&sumS[qi * 2],     s1a); atomicAdd(&sqS[qi * 2],     s2a);
    atomicAdd(&sumS[qi * 2 + 1], s1b); atomicAdd(&sqS[qi * 2 + 1], s2b);
    __syncthreads();
    if (t < 128) {
        float mu  = sumS[t] * (1.f / DIM);
        float var = sqS[t] * (1.f / DIM) - mu * mu;
        float r   = rsqrtf(var + EPS_LN);
        muS[t] = mu; rS[t] = r;
        g_mu[b * HW + q0 + t] = mu;
        g_r [b * HW + q0 + t] = r;
    }
    __syncthreads();

    // epilogue: y -> gelu -> logits
#pragma unroll
    for (int mt = 0; mt < 2; mt++) {
#pragma unroll
        for (int hf = 0; hf < 2; hf++) {
            int ql   = wm * 32 + mt * 16 + hf * 8 + gid;
            float mu = muS[ql], r = rS[ql];
            float pl[NTOK];
#pragma unroll
            for (int n = 0; n < NTOK; n++) pl[n] = 0.f;
#pragma unroll
            for (int nt = 0; nt < 6; nt++) {
#pragma unroll
                for (int ch = 0; ch < 2; ch++) {
                    int i   = wn * 48 + nt * 8 + tid * 2 + ch;
                    float v = acc[mt][nt][hf * 2 + ch];
                    float y = r * (v - mu * colsumS[i]) + bw1S[i];
                    float h = 0.5f * y * (1.f + erff(y * 0.70710678f));
#pragma unroll
                    for (int n = 0; n < NTOK; n++) pl[n] += h * w2S[i * NTOK + n];
                }
            }
#pragma unroll
            for (int n = 0; n < NTOK; n++) {
                pl[n] += __shfl_xor_sync(0xffffffffu, pl[n], 1);
                pl[n] += __shfl_xor_sync(0xffffffffu, pl[n], 2);
            }
            if (tid == 0) {
#pragma unroll
                for (int n = 0; n < NTOK; n++)
                    atomicAdd(&logitsS[ql * NTOK + n], pl[n]);
            }
        }
    }
    __syncthreads();
    for (int idx = t; idx < 128 * NTOK; idx += 256) {
        int n = idx >> 7, q = idx & 127;
        g_logitsT[((size_t)b * NTOK + n) * HW + q0 + q] = logitsS[q * NTOK + n];
    }
}

// ---------------- pass B: softmax over tokens, per (b, n) --------------------
__global__ void passB_kernel()
{
    int b = blockIdx.x;
    int w = threadIdx.x >> 5, lane = threadIdx.x & 31;   // 8 warps -> 8 logits
    const float* lp  = g_logitsT + ((size_t)b * NTOK + w) * HW;
    const float* mup = g_mu + (size_t)b * HW;
    const float* rp  = g_r  + (size_t)b * HW;

    float m = -1e30f;
    for (int j = 0; j < 32; j++) m = fmaxf(m, lp[lane + j * 32]);
#pragma unroll
    for (int o = 16; o; o >>= 1) m = fmaxf(m, __shfl_xor_sync(0xffffffffu, m, o));

    float Z = 0.f, Sm = 0.f;
    for (int j = 0; j < 32; j++) {
        int p  = lane + j * 32;
        float e = expf(lp[p] - m);
        Z  += e;
        Sm += mup[p] * rp[p] * e;
    }
#pragma unroll
    for (int o = 16; o; o >>= 1) {
        Z  += __shfl_xor_sync(0xffffffffu, Z,  o);
        Sm += __shfl_xor_sync(0xffffffffu, Sm, o);
    }
    float invZ = 1.f / Z;
    float* ap = g_attnwT + ((size_t)b * NTOK + w) * HW;
    for (int j = 0; j < 32; j++) {
        int p  = lane + j * 32;
        float e = expf(lp[p] - m);
        ap[p] = rp[p] * e * invZ;
    }
    if (lane == 0) g_S[b * NTOK + w] = Sm * invZ;
}

// ---------------- pass C: out[b,c,n] via weighted pooling of raw x -----------
__global__ __launch_bounds__(256, 2) void passC_kernel(
    const float* __restrict__ x, const float* __restrict__ gamma,
    const float* __restrict__ beta, float* __restrict__ out)
{
    __shared__ float awS[NTOK * HW];   // 32 KB
    __shared__ float Ss[NTOK];
    int t   = threadIdx.x;
    int blk = blockIdx.x;
    int b   = blk >> 3, ct = blk & 7;

    for (int i = t; i < NTOK * HW; i += 256)
        awS[i] = g_attnwT[(size_t)b * NTOK * HW + i];
    if (t < NTOK) Ss[t] = g_S[b * NTOK + t];
    __syncthreads();

    int w = t >> 5, lane = t & 31;
    int c0 = ct * 96;
    for (int it = 0; it < 3; it++) {
        int c = c0 + it * 32 + w * 4;           // warp handles 4 channels
        const float* xb = x + ((size_t)b * DIM + c) * HW;
        ull acc2[4][NTOK];
#pragma unroll
        for (int k = 0; k < 4; k++)
#pragma unroll
            for (int n = 0; n < NTOK; n++) acc2[k][n] = 0ull;

#pragma unroll
        for (int j = 0; j < 8; j++) {
            int q4 = lane * 4 + j * 128;
            ulonglong2 xp[4];
#pragma unroll
            for (int k = 0; k < 4; k++)
                xp[k] = *(const ulonglong2*)(xb + (size_t)k * HW + q4);
#pragma unroll
            for (int n = 0; n < NTOK; n++) {
                ulonglong2 apx = *(const ulonglong2*)(awS + n * HW + q4);
#pragma unroll
                for (int k = 0; k < 4; k++) {
                    fma2(acc2[k][n], xp[k].x, apx.x);
                    fma2(acc2[k][n], xp[k].y, apx.y);
                }
            }
        }
#pragma unroll
        for (int k = 0; k < 4; k++) {
#pragma unroll
            for (int n = 0; n < NTOK; n++) {
                float lo = __int_as_float((unsigned)(acc2[k][n] & 0xffffffffull));
                float hi = __int_as_float((unsigned)(acc2[k][n] >> 32));
                float v  = lo + hi;
#pragma unroll
                for (int o = 16; o; o >>= 1) v += __shfl_xor_sync(0xffffffffu, v, o);
                if (lane == 0) {
                    float g  = gamma[c + k], be = beta[c + k];
                    out[(((size_t)b * DIM) + (c + k)) * NTOK + n] =
                        (g * (v - Ss[n]) + be) * (1.f / 1024.f);
                }
            }
        }
    }
}

// ---------------- launcher ----------------------------------------------------
extern "C" void kernel_launch(void* const* d_in, const int* in_sizes, int n_in,
                              void* d_out, int out_size)
{
    const float* x     = (const float*)d_in[0];
    const float* gamma = (const float*)d_in[1];
    const float* beta  = (const float*)d_in[2];
    const float* w1    = (const float*)d_in[3];
    const float* b1    = (const float*)d_in[4];
    const float* w2    = (const float*)d_in[5];
    // d_in[6] = b2: constant shift before softmax over tokens -> exactly cancels.
    float* out = (float*)d_out;

    setup_kernel<<<INNER, 256>>>(w1, gamma, beta, b1);
    passA_kernel<<<NB * 8, 256>>>(x, w2);
    passB_kernel<<<NB, 256>>>();
    passC_kernel<<<NB * 8, 256>>>(x, gamma, beta, out);
}

// round 3
// speedup vs baseline: 1.0827x; 1.0827x over previous
#include <cuda_runtime.h>
#include <cuda_bf16.h>
#include <cstdint>

#define DIM   768
#define INNER 96
#define NTOK  8
#define HW    1024
#define NB    64
#define EPS_LN 1e-5f

typedef unsigned long long ull;

// ---------------- scratch (device globals; no allocation allowed) ------------
__device__ __nv_bfloat16 g_Wt[INNER * DIM];        // W1*gamma, bf16, [i][c]
__device__ float g_colsum[INNER];
__device__ float g_bw1[INNER];
__device__ float g_r[NB * HW];
__device__ float g_mu[NB * HW];
__device__ float g_logitsT[NB * NTOK * HW];
__device__ float g_attnwT[NB * NTOK * HW];         // r_p * attn[p,n], [b][n][p]
__device__ float g_S[NB * NTOK];

// ---------------- helpers ----------------------------------------------------
__device__ __forceinline__ void mma_bf16(float* d,
    uint32_t a0, uint32_t a1, uint32_t a2, uint32_t a3,
    uint32_t b0, uint32_t b1)
{
    asm volatile(
        "mma.sync.aligned.m16n8k16.row.col.f32.bf16.bf16.f32 "
        "{%0,%1,%2,%3}, {%4,%5,%6,%7}, {%8,%9}, {%0,%1,%2,%3};"
        : "+f"(d[0]), "+f"(d[1]), "+f"(d[2]), "+f"(d[3])
        : "r"(a0), "r"(a1), "r"(a2), "r"(a3), "r"(b0), "r"(b1));
}

__device__ __forceinline__ void ldsm_x4(uint32_t* r, uint32_t addr) {
    asm volatile("ldmatrix.sync.aligned.m8n8.x4.shared.b16 {%0,%1,%2,%3}, [%4];"
        : "=r"(r[0]), "=r"(r[1]), "=r"(r[2]), "=r"(r[3]) : "r"(addr));
}
__device__ __forceinline__ void ldsm_x2(uint32_t* r, uint32_t addr) {
    asm volatile("ldmatrix.sync.aligned.m8n8.x2.shared.b16 {%0,%1}, [%2];"
        : "=r"(r[0]), "=r"(r[1]) : "r"(addr));
}

__device__ __forceinline__ void fma2(ull& d, ull a, ull b) {
    asm volatile("fma.rn.f32x2 %0, %1, %2, %0;" : "+l"(d) : "l"(a), "l"(b));
}

// ---------------- setup: fold gamma into W1, precompute column sums ----------
__global__ void setup_kernel(const float* __restrict__ w1,
                             const float* __restrict__ gamma,
                             const float* __restrict__ beta,
                             const float* __restrict__ b1)
{
    int i = blockIdx.x;
    int t = threadIdx.x;
    float a = 0.f, bs = 0.f;
    for (int c = t; c < DIM; c += 256) {
        float w  = w1[c * INNER + i];
        float gw = gamma[c] * w;
        g_Wt[i * DIM + c] = __float2bfloat16(gw);
        a  += gw;
        bs += beta[c] * w;
    }
    __shared__ float ra[256], rb[256];
    ra[t] = a; rb[t] = bs;
    __syncthreads();
    for (int s = 128; s > 0; s >>= 1) {
        if (t < s) { ra[t] += ra[t + s]; rb[t] += rb[t + s]; }
        __syncthreads();
    }
    if (t == 0) { g_colsum[i] = ra[0]; g_bw1[i] = rb[0] + b1[i]; }
}

// ---------------- pass A: LN stats + MLP logits, pipelined bf16 mma ----------
constexpr int XP = 40;   // bf16 pitch; 80B rows: 16B-aligned, ldmatrix conflict-free
constexpr int WP = 40;

__global__ __launch_bounds__(256, 2) void passA_kernel(
    const float* __restrict__ x, const float* __restrict__ w2)
{
    __shared__ __nv_bfloat16 Xs[2][128 * XP];   // 20 KB
    __shared__ __nv_bfloat16 Ws[2][INNER * WP]; // 15 KB
    __shared__ float logitsS[128 * NTOK];
    __shared__ float sumS[128], sqS[128], muS[128], rS[128];
    __shared__ float w2S[INNER * NTOK];
    __shared__ float colsumS[INNER], bw1S[INNER];

    int t   = threadIdx.x;
    int blk = blockIdx.x;
    int b   = blk >> 3;
    int q0  = (blk & 7) << 7;

    for (int i = t; i < 128 * NTOK; i += 256) logitsS[i] = 0.f;
    if (t < 128) { sumS[t] = 0.f; sqS[t] = 0.f; }
    for (int i = t; i < INNER * NTOK; i += 256) w2S[i] = w2[i];
    if (t < INNER) { colsumS[t] = g_colsum[t]; bw1S[t] = g_bw1[t]; }

    int qi = t & 63;        // token pair: rows 2qi, 2qi+1
    int ci = t >> 6;        // channel slice 0..3 (8 channels each)
    const float* xb = x + ((size_t)b * DIM) * HW + q0 + qi * 2;

    float s1a = 0.f, s1b = 0.f, s2a = 0.f, s2b = 0.f;
    float acc[2][6][4];
#pragma unroll
    for (int mt = 0; mt < 2; mt++)
#pragma unroll
        for (int nt = 0; nt < 6; nt++)
#pragma unroll
            for (int r = 0; r < 4; r++) acc[mt][nt][r] = 0.f;

    int w    = t >> 5, lane = t & 31;
    int wm   = w & 3,  wn   = w >> 2;   // warp tile: 32 q x 48 i
    int gid  = lane >> 2, tid = lane & 3;
    int wi   = t >> 1, whf = t & 1;

    // ldmatrix base addresses (byte, shared state space), buffer 0
    uint32_t aAddr0 = (uint32_t)__cvta_generic_to_shared(
        &Xs[0][(wm * 32 + (lane & 15)) * XP + (lane >> 4) * 8]);
    uint32_t aAddr1 = aAddr0 + 16 * XP * 2;   // mt=1: +16 rows
    uint32_t bAddr  = (uint32_t)__cvta_generic_to_shared(
        &Ws[0][(wn * 48 + (lane & 7)) * WP + ((lane >> 3) & 1) * 8]);
    const uint32_t XBUF = 128 * XP * 2;       // byte stride between X buffers
    const uint32_t WBUF = INNER * WP * 2;

    float2 xv[8];
    uint4 wv0, wv1;
    // prologue loads (kc = 0)
#pragma unroll
    for (int j = 0; j < 8; j++)
        xv[j] = *(const float2*)(xb + (size_t)(ci * 8 + j) * HW);
    if (t < 192) {
        const uint4* src = (const uint4*)(g_Wt + wi * DIM + whf * 16);
        wv0 = src[0]; wv1 = src[1];
    }

    for (int kc = 0; kc < 24; kc++) {
        int buf = kc & 1;
        // stats + convert + packed store (2x STS.128 per thread)
#pragma unroll
        for (int j = 0; j < 8; j++) {
            s1a += xv[j].x; s2a += xv[j].x * xv[j].x;
            s1b += xv[j].y; s2b += xv[j].y * xv[j].y;
        }
        __nv_bfloat162 p0[4], p1[4];
#pragma unroll
        for (int j = 0; j < 4; j++) {
            p0[j] = __floats2bfloat162_rn(xv[2*j].x, xv[2*j+1].x);
            p1[j] = __floats2bfloat162_rn(xv[2*j].y, xv[2*j+1].y);
        }
        *(uint4*)&Xs[buf][(qi * 2)     * XP + ci * 8] = *(uint4*)p0;
        *(uint4*)&Xs[buf][(qi * 2 + 1) * XP + ci * 8] = *(uint4*)p1;
        if (t < 192) {
            uint4* dst = (uint4*)&Ws[buf][wi * WP + whf * 16];
            dst[0] = wv0; dst[1] = wv1;
        }
        __syncthreads();

        // prefetch next k-chunk (overlaps with MMAs below)
        if (kc < 23) {
            int c0 = (kc + 1) * 32;
#pragma unroll
            for (int j = 0; j < 8; j++)
                xv[j] = *(const float2*)(xb + (size_t)(c0 + ci * 8 + j) * HW);
            if (t < 192) {
                const uint4* src = (const uint4*)(g_Wt + wi * DIM + c0 + whf * 16);
                wv0 = src[0]; wv1 = src[1];
            }
        }

        uint32_t xo = buf * XBUF, wo = buf * WBUF;
#pragma unroll
        for (int ks = 0; ks < 2; ks++) {
            uint32_t af0[4], af1[4];
            ldsm_x4(af0, aAddr0 + xo + ks * 32);
            ldsm_x4(af1, aAddr1 + xo + ks * 32);
            uint32_t bfrag[6][2];
#pragma unroll
            for (int nt = 0; nt < 6; nt++)
                ldsm_x2(bfrag[nt], bAddr + wo + nt * 8 * WP * 2 + ks * 32);
#pragma unroll
            for (int nt = 0; nt < 6; nt++) {
                mma_bf16(acc[0][nt], af0[0], af0[1], af0[2], af0[3],
                         bfrag[nt][0], bfrag[nt][1]);
                mma_bf16(acc[1][nt], af1[0], af1[1], af1[2], af1[3],
                         bfrag[nt][0], bfrag[nt][1]);
            }
        }
    }

    // token stats
    atomicAdd(&sumS[qi * 2],     s1a); atomicAdd(&sqS[qi * 2],     s2a);
    atomicAdd(&sumS[qi * 2 + 1], s1b); atomicAdd(&sqS[qi * 2 + 1], s2b);
    __syncthreads();
    if (t < 128) {
        float mu  = sumS[t] * (1.f / DIM);
        float var = sqS[t] * (1.f / DIM) - mu * mu;
        float r   = rsqrtf(var + EPS_LN);
        muS[t] = mu; rS[t] = r;
        g_mu[b * HW + q0 + t] = mu;
        g_r [b * HW + q0 + t] = r;
    }
    __syncthreads();

    // epilogue: y -> gelu -> logits
#pragma unroll
    for (int mt = 0; mt < 2; mt++) {
#pragma unroll
        for (int hf = 0; hf < 2; hf++) {
            int ql   = wm * 32 + mt * 16 + hf * 8 + gid;
            float mu = muS[ql], r = rS[ql];
            float pl[NTOK];
#pragma unroll
            for (int n = 0; n < NTOK; n++) pl[n] = 0.f;
#pragma unroll
            for (int nt = 0; nt < 6; nt++) {
#pragma unroll
                for (int ch = 0; ch < 2; ch++) {
                    int i   = wn * 48 + nt * 8 + tid * 2 + ch;
                    float v = acc[mt][nt][hf * 2 + ch];
                    float y = r * (v - mu * colsumS[i]) + bw1S[i];
                    float h = 0.5f * y * (1.f + erff(y * 0.70710678f));
#pragma unroll
                    for (int n = 0; n < NTOK; n++) pl[n] += h * w2S[i * NTOK + n];
                }
            }
#pragma unroll
            for (int n = 0; n < NTOK; n++) {
                pl[n] += __shfl_xor_sync(0xffffffffu, pl[n], 1);
                pl[n] += __shfl_xor_sync(0xffffffffu, pl[n], 2);
            }
            if (tid == 0) {
#pragma unroll
                for (int n = 0; n < NTOK; n++)
                    atomicAdd(&logitsS[ql * NTOK + n], pl[n]);
            }
        }
    }
    __syncthreads();
    for (int idx = t; idx < 128 * NTOK; idx += 256) {
        int n = idx >> 7, q = idx & 127;
        g_logitsT[((size_t)b * NTOK + n) * HW + q0 + q] = logitsS[q * NTOK + n];
    }
}

// ---------------- pass B: softmax over tokens, per (b, n) --------------------
__global__ void passB_kernel()
{
    int b = blockIdx.x;
    int w = threadIdx.x >> 5, lane = threadIdx.x & 31;
    const float* lp  = g_logitsT + ((size_t)b * NTOK + w) * HW;
    const float* mup = g_mu + (size_t)b * HW;
    const float* rp  = g_r  + (size_t)b * HW;

    float m = -1e30f;
    for (int j = 0; j < 32; j++) m = fmaxf(m, lp[lane + j * 32]);
#pragma unroll
    for (int o = 16; o; o >>= 1) m = fmaxf(m, __shfl_xor_sync(0xffffffffu, m, o));

    float Z = 0.f, Sm = 0.f;
    for (int j = 0; j < 32; j++) {
        int p  = lane + j * 32;
        float e = expf(lp[p] - m);
        Z  += e;
        Sm += mup[p] * rp[p] * e;
    }
#pragma unroll
    for (int o = 16; o; o >>= 1) {
        Z  += __shfl_xor_sync(0xffffffffu, Z,  o);
        Sm += __shfl_xor_sync(0xffffffffu, Sm, o);
    }
    float invZ = 1.f / Z;
    float* ap = g_attnwT + ((size_t)b * NTOK + w) * HW;
    for (int j = 0; j < 32; j++) {
        int p  = lane + j * 32;
        float e = expf(lp[p] - m);
        ap[p] = rp[p] * e * invZ;
    }
    if (lane == 0) g_S[b * NTOK + w] = Sm * invZ;
}

// ---------------- pass C: out[b,c,n] weighted pooling, reversed batches ------
__global__ __launch_bounds__(256, 3) void passC_kernel(
    const float* __restrict__ x, const float* __restrict__ gamma,
    const float* __restrict__ beta, float* __restrict__ out)
{
    __shared__ float awS[NTOK * HW];   // 32 KB
    __shared__ float Ss[NTOK];
    int t   = threadIdx.x;
    int blk = blockIdx.x;
    int b   = (NB - 1) - (blk / 48);   // reversed: hit passA's L2 tail
    int ct  = blk % 48;                // 16 channels per block

    for (int i = t * 4; i < NTOK * HW; i += 1024)
        *(float4*)&awS[i] = *(const float4*)&g_attnwT[(size_t)b * NTOK * HW + i];
    if (t < NTOK) Ss[t] = g_S[b * NTOK + t];
    __syncthreads();

    int w = t >> 5, lane = t & 31;
    int c = ct * 16 + w * 2;           // warp handles 2 channels
    const float* xb = x + ((size_t)b * DIM + c) * HW;

    ull acc2[2][NTOK];
#pragma unroll
    for (int k = 0; k < 2; k++)
#pragma unroll
        for (int n = 0; n < NTOK; n++) acc2[k][n] = 0ull;

#pragma unroll
    for (int j = 0; j < 8; j++) {
        int q4 = lane * 4 + j * 128;
        ulonglong2 xp0 = *(const ulonglong2*)(xb + q4);
        ulonglong2 xp1 = *(const ulonglong2*)(xb + HW + q4);
#pragma unroll
        for (int n = 0; n < NTOK; n++) {
            ulonglong2 a = *(const ulonglong2*)(awS + n * HW + q4);
            fma2(acc2[0][n], xp0.x, a.x);
            fma2(acc2[0][n], xp0.y, a.y);
            fma2(acc2[1][n], xp1.x, a.x);
            fma2(acc2[1][n], xp1.y, a.y);
        }
    }
#pragma unroll
    for (int k = 0; k < 2; k++) {
#pragma unroll
        for (int n = 0; n < NTOK; n++) {
            float lo = __int_as_float((unsigned)(acc2[k][n] & 0xffffffffull));
            float hi = __int_as_float((unsigned)(acc2[k][n] >> 32));
            float v  = lo + hi;
#pragma unroll
            for (int o = 16; o; o >>= 1) v += __shfl_xor_sync(0xffffffffu, v, o);
            if (lane == 0) {
                float g  = gamma[c + k], be = beta[c + k];
                out[(((size_t)b * DIM) + (c + k)) * NTOK + n] =
                    (g * (v - Ss[n]) + be) * (1.f / 1024.f);
            }
        }
    }
}

// ---------------- launcher ----------------------------------------------------
extern "C" void kernel_launch(void* const* d_in, const int* in_sizes, int n_in,
                              void* d_out, int out_size)
{
    const float* x     = (const float*)d_in[0];
    const float* gamma = (const float*)d_in[1];
    const float* beta  = (const float*)d_in[2];
    const float* w1    = (const float*)d_in[3];
    const float* b1    = (const float*)d_in[4];
    const float* w2    = (const float*)d_in[5];
    // d_in[6] = b2: constant shift before token softmax -> cancels exactly.
    float* out = (float*)d_out;

    setup_kernel<<<INNER, 256>>>(w1, gamma, beta, b1);
    passA_kernel<<<NB * 8, 256>>>(x, w2);
    passB_kernel<<<NB, 256>>>();
    passC_kernel<<<NB * 48, 256>>>(x, gamma, beta, out);
}